// round 8
// baseline (speedup 1.0000x reference)
#include <cuda_runtime.h>
#include <cuda_bf16.h>

#define D_MODEL 1024
#define NHEADS  16
#define HDIM    64
#define SEQ     2048
#define BATCH   2
#define ROWS    (BATCH*SEQ)   // 4096
#define NQKV    (3*D_MODEL)   // 3072

// Scratch (device globals: no allocation allowed in kernel_launch)
__device__ float g_inv[ROWS];             // per-row inv_rms
__device__ float g_qkv[ROWS * NQKV];      // fused qkv, row-major [4096, 3072]
__device__ float g_ctx[ROWS * D_MODEL];   // attention output, [b*l, d]

// ---------------------------------------------------------------------------
// Helpers
// ---------------------------------------------------------------------------
__device__ __forceinline__ unsigned f2tf32(float f) {
    unsigned u;
    asm("cvt.rna.tf32.f32 %0, %1;" : "=r"(u) : "f"(f));
    return u;
}

__device__ __forceinline__ unsigned pack_bf2(float lo, float hi) {
    __nv_bfloat162 t = __floats2bfloat162_rn(lo, hi);
    return *reinterpret_cast<unsigned*>(&t);
}

__device__ __forceinline__ void mma_bf16(float* c, const unsigned* a, unsigned b0, unsigned b1) {
    asm volatile(
        "mma.sync.aligned.m16n8k16.row.col.f32.bf16.bf16.f32 "
        "{%0,%1,%2,%3}, {%4,%5,%6,%7}, {%8,%9}, {%0,%1,%2,%3};"
        : "+f"(c[0]), "+f"(c[1]), "+f"(c[2]), "+f"(c[3])
        : "r"(a[0]), "r"(a[1]), "r"(a[2]), "r"(a[3]), "r"(b0), "r"(b1));
}

__device__ __forceinline__ void mma_tf32(float* c, const unsigned* a, unsigned b0, unsigned b1) {
    asm volatile(
        "mma.sync.aligned.m16n8k8.row.col.f32.tf32.tf32.f32 "
        "{%0,%1,%2,%3}, {%4,%5,%6,%7}, {%8,%9}, {%0,%1,%2,%3};"
        : "+f"(c[0]), "+f"(c[1]), "+f"(c[2]), "+f"(c[3])
        : "r"(a[0]), "r"(a[1]), "r"(a[2]), "r"(a[3]), "r"(b0), "r"(b1));
}

// ---------------------------------------------------------------------------
// RMS inverse: one block per row of 1024 floats; writes only inv_rms scalar.
// ---------------------------------------------------------------------------
__global__ __launch_bounds__(256) void rms_inv_kernel(const float* __restrict__ x) {
    int row = blockIdx.x;
    const float4* xr = reinterpret_cast<const float4*>(x + (size_t)row * D_MODEL);
    float4 v = xr[threadIdx.x];
    float ss = v.x * v.x + v.y * v.y + v.z * v.z + v.w * v.w;
    __shared__ float red[8];
    #pragma unroll
    for (int o = 16; o; o >>= 1) ss += __shfl_xor_sync(0xffffffffu, ss, o);
    if ((threadIdx.x & 31) == 0) red[threadIdx.x >> 5] = ss;
    __syncthreads();
    if (threadIdx.x == 0) {
        float s = 0.f;
        #pragma unroll
        for (int i = 0; i < 8; i++) s += red[i];
        g_inv[row] = rsqrtf(s * (1.0f / D_MODEL) + 1e-6f);
    }
}

// ---------------------------------------------------------------------------
// Generic TF32 GEMM: C[M,N] = A'[M,K] @ B[K,N] (+ Res), all row-major fp32,
// where A'[r][c] = A[r][c] * rowscale[r] * colscale[c] if rowscale != nullptr
// (fused RMSNorm), else A' = A.
// BM=128, BN=128, BK=32, 256 threads (8 warps: 4 along M x 2 along N;
// each warp owns a 32x64 C region). Register-prefetch software pipeline +
// ping-pong smem double-buffer (ONE barrier per K-tile). Dynamic smem 70 KB.
// ---------------------------------------------------------------------------
#define GBM 128
#define GBN 128
#define GBK 32
#define AS_LD 36    // padded stride (words): bank = 4g+q, conflict-free a-frag LDS
#define BS_LD 136   // padded stride (words): bank = 8q+g, conflict-free b-frag LDS
#define AS_BUF (GBM * AS_LD)                       // words per A buffer
#define BS_BUF (GBK * BS_LD)                       // words per B buffer
#define GEMM_SMEM_BYTES ((2 * AS_BUF + 2 * BS_BUF) * 4)   // 71680

__global__ __launch_bounds__(256) void gemm_tf32(const float* __restrict__ A,
                                                 const float* __restrict__ B,
                                                 const float* __restrict__ Res,
                                                 const float* __restrict__ rowscale,
                                                 const float* __restrict__ colscale,
                                                 float* __restrict__ C,
                                                 int M, int N, int K) {
    extern __shared__ unsigned smem_u[];
    unsigned* AsAll = smem_u;                 // 2 buffers of AS_BUF
    unsigned* BsAll = smem_u + 2 * AS_BUF;    // 2 buffers of BS_BUF

    int tid  = threadIdx.x;
    int lane = tid & 31, w = tid >> 5;
    int g = lane >> 2, q = lane & 3;
    int wm = w & 3, wn = w >> 2;           // wm 0..3 (M), wn 0..1 (N)
    int bm = blockIdx.y * GBM, bn = blockIdx.x * GBN;

    float acc[2][8][4] = {};

    int ar = tid >> 1, ac = (tid & 1) * 16;   // A stage: 4x contiguous float4
    int br = tid >> 3, bj = tid & 7;          // B stage: row br, 4x float4 at chunks i*8+bj

    // Row scale for this thread's staging row (constant across K-tiles)
    float rs = rowscale ? rowscale[bm + ar] : 1.0f;

    // Prologue: prefetch tile kt=0
    float4 pa[4], pb[4];
    {
        const float4* ag = reinterpret_cast<const float4*>(A + (size_t)(bm + ar) * K + ac);
        #pragma unroll
        for (int i = 0; i < 4; i++) pa[i] = ag[i];
        const float4* bg = reinterpret_cast<const float4*>(B + (size_t)br * N + bn);
        #pragma unroll
        for (int i = 0; i < 4; i++) pb[i] = bg[i * 8 + bj];
    }

    int buf = 0;
    for (int kt = 0; kt < K; kt += GBK) {
        unsigned* As = AsAll + buf * AS_BUF;
        unsigned* Bs = BsAll + buf * BS_BUF;

        // Store prefetched tile to smem (with optional norm fusion + tf32 cvt)
        #pragma unroll
        for (int i = 0; i < 4; i++) {
            float4 s = pa[i];
            if (rowscale) {
                const float4 cw = __ldg(reinterpret_cast<const float4*>(colscale + kt + ac + i * 4));
                s.x *= rs * cw.x; s.y *= rs * cw.y;
                s.z *= rs * cw.z; s.w *= rs * cw.w;
            }
            unsigned* d = &As[ar * AS_LD + ac + i * 4];
            d[0] = f2tf32(s.x); d[1] = f2tf32(s.y);
            d[2] = f2tf32(s.z); d[3] = f2tf32(s.w);
        }
        #pragma unroll
        for (int i = 0; i < 4; i++) {
            unsigned* d = &Bs[br * BS_LD + (i * 8 + bj) * 4];
            d[0] = f2tf32(pb[i].x); d[1] = f2tf32(pb[i].y);
            d[2] = f2tf32(pb[i].z); d[3] = f2tf32(pb[i].w);
        }
        __syncthreads();   // single barrier per tile (ping-pong makes tail barrier unnecessary)

        // Prefetch next tile (overlaps with MMA compute below)
        int kn = kt + GBK;
        if (kn < K) {
            const float4* ag = reinterpret_cast<const float4*>(A + (size_t)(bm + ar) * K + kn + ac);
            #pragma unroll
            for (int i = 0; i < 4; i++) pa[i] = ag[i];
            const float4* bg = reinterpret_cast<const float4*>(B + (size_t)(kn + br) * N + bn);
            #pragma unroll
            for (int i = 0; i < 4; i++) pb[i] = bg[i * 8 + bj];
        }

        #pragma unroll
        for (int ks = 0; ks < 4; ks++) {
            unsigned a[2][4], b[8][2];
            #pragma unroll
            for (int mt = 0; mt < 2; mt++) {
                int r = wm * 32 + mt * 16;
                a[mt][0] = As[(r + g)     * AS_LD + ks * 8 + q];
                a[mt][1] = As[(r + g + 8) * AS_LD + ks * 8 + q];
                a[mt][2] = As[(r + g)     * AS_LD + ks * 8 + q + 4];
                a[mt][3] = As[(r + g + 8) * AS_LD + ks * 8 + q + 4];
            }
            #pragma unroll
            for (int nt = 0; nt < 8; nt++) {
                int c = wn * 64 + nt * 8 + g;
                b[nt][0] = Bs[(ks * 8 + q)     * BS_LD + c];
                b[nt][1] = Bs[(ks * 8 + q + 4) * BS_LD + c];
            }
            #pragma unroll
            for (int mt = 0; mt < 2; mt++)
                #pragma unroll
                for (int nt = 0; nt < 8; nt++)
                    mma_tf32(acc[mt][nt], a[mt], b[nt][0], b[nt][1]);
        }
        buf ^= 1;
    }

    #pragma unroll
    for (int mt = 0; mt < 2; mt++) {
        int r0 = bm + wm * 32 + mt * 16 + g;
        #pragma unroll
        for (int nt = 0; nt < 8; nt++) {
            int c = bn + wn * 64 + nt * 8 + q * 2;
            float2 v0 = make_float2(acc[mt][nt][0], acc[mt][nt][1]);
            float2 v1 = make_float2(acc[mt][nt][2], acc[mt][nt][3]);
            if (Res) {
                float2 r0v = *reinterpret_cast<const float2*>(Res + (size_t)r0 * N + c);
                float2 r1v = *reinterpret_cast<const float2*>(Res + (size_t)(r0 + 8) * N + c);
                v0.x += r0v.x; v0.y += r0v.y;
                v1.x += r1v.x; v1.y += r1v.y;
            }
            *reinterpret_cast<float2*>(C + (size_t)r0 * N + c) = v0;
            *reinterpret_cast<float2*>(C + (size_t)(r0 + 8) * N + c) = v1;
        }
    }
}

// ---------------------------------------------------------------------------
// Flash attention: per (b,head), BM=128 q-rows per block, BN=64 keys per step.
// bf16 mma m16n8k16; Q pre-scaled by 1/8; K staged padded; V staged transposed.
// 256 threads (8 warps, 16 q-rows each). K/V register prefetch + ping-pong
// smem double-buffer (ONE barrier per KV-tile). 36 KB static smem.
// ---------------------------------------------------------------------------
#define KS_LD 72   // bf16 elements per padded row (conflict-free 32-bit LDS)
#define KV_BUF (64 * KS_LD)

__global__ __launch_bounds__(256) void attn_kernel() {
    __shared__ __nv_bfloat16 Ks[2 * KV_BUF];   // Ks[key][d], 2 buffers
    __shared__ __nv_bfloat16 Vs[2 * KV_BUF];   // Vs[d][key]  (transposed), 2 buffers

    int tid  = threadIdx.x;
    int lane = tid & 31, w = tid >> 5;        // w in 0..7
    int g = lane >> 2, q = lane & 3;
    int bh = blockIdx.y;
    int b = bh >> 4, h = bh & 15;
    int q0 = blockIdx.x * 128;

    const float* qp = g_qkv + (size_t)(b * SEQ) * NQKV + h * HDIM;
    const float* kp = qp + D_MODEL;
    const float* vp = qp + 2 * D_MODEL;

    // Q fragments: 4 k16-tiles x 4 regs, pre-scaled by 1/sqrt(64)=0.125 (exact in bf16)
    unsigned aq[4][4];
    {
        const float s = 0.125f;
        int r0 = q0 + w * 16 + g;
        #pragma unroll
        for (int kt = 0; kt < 4; kt++) {
            int c = kt * 16 + q * 2;
            float2 v00 = *reinterpret_cast<const float2*>(qp + (size_t)r0 * NQKV + c);
            float2 v01 = *reinterpret_cast<const float2*>(qp + (size_t)r0 * NQKV + c + 8);
            float2 v10 = *reinterpret_cast<const float2*>(qp + (size_t)(r0 + 8) * NQKV + c);
            float2 v11 = *reinterpret_cast<const float2*>(qp + (size_t)(r0 + 8) * NQKV + c + 8);
            aq[kt][0] = pack_bf2(v00.x * s, v00.y * s);
            aq[kt][1] = pack_bf2(v10.x * s, v10.y * s);
            aq[kt][2] = pack_bf2(v01.x * s, v01.y * s);
            aq[kt][3] = pack_bf2(v11.x * s, v11.y * s);
        }
    }

    float oacc[8][4] = {};
    float m0 = -1e30f, m1 = -1e30f, l0 = 0.f, l1 = 0.f;

    // Staging split over 256 threads: key-row lr (0..63), d-cols [lc, lc+16)
    int lr = tid >> 2, lc = (tid & 3) * 16;

    // Prologue: prefetch K/V tile n0=0 into registers (4 float4 each)
    float4 kf[4], vf[4];
    #pragma unroll
    for (int i = 0; i < 4; i++) {
        kf[i] = *reinterpret_cast<const float4*>(kp + (size_t)lr * NQKV + lc + i * 4);
        vf[i] = *reinterpret_cast<const float4*>(vp + (size_t)lr * NQKV + lc + i * 4);
    }

    int buf = 0;
    for (int n0 = 0; n0 < SEQ; n0 += 64) {
        __nv_bfloat16* Kb = Ks + buf * KV_BUF;
        __nv_bfloat16* Vb = Vs + buf * KV_BUF;

        // Stage prefetched K (natural) and V (transposed) as bf16
        #pragma unroll
        for (int i = 0; i < 4; i++) {
            __nv_bfloat162* d = reinterpret_cast<__nv_bfloat162*>(&Kb[lr * KS_LD + lc + i * 4]);
            d[0] = __floats2bfloat162_rn(kf[i].x, kf[i].y);
            d[1] = __floats2bfloat162_rn(kf[i].z, kf[i].w);
            Vb[(lc + i * 4 + 0) * KS_LD + lr] = __float2bfloat16(vf[i].x);
            Vb[(lc + i * 4 + 1) * KS_LD + lr] = __float2bfloat16(vf[i].y);
            Vb[(lc + i * 4 + 2) * KS_LD + lr] = __float2bfloat16(vf[i].z);
            Vb[(lc + i * 4 + 3) * KS_LD + lr] = __float2bfloat16(vf[i].w);
        }
        __syncthreads();   // single barrier per tile (ping-pong buffers)

        // Prefetch next tile (overlaps with compute below)
        int nn = n0 + 64;
        if (nn < SEQ) {
            #pragma unroll
            for (int i = 0; i < 4; i++) {
                kf[i] = *reinterpret_cast<const float4*>(kp + (size_t)(nn + lr) * NQKV + lc + i * 4);
                vf[i] = *reinterpret_cast<const float4*>(vp + (size_t)(nn + lr) * NQKV + lc + i * 4);
            }
        }

        // S = (Q*scale) @ K^T   (16 q-rows x 64 keys per warp)
        float sacc[8][4] = {};
        #pragma unroll
        for (int kt = 0; kt < 4; kt++) {
            #pragma unroll
            for (int nt = 0; nt < 8; nt++) {
                unsigned b0 = *reinterpret_cast<const unsigned*>(&Kb[(nt * 8 + g) * KS_LD + kt * 16 + q * 2]);
                unsigned b1 = *reinterpret_cast<const unsigned*>(&Kb[(nt * 8 + g) * KS_LD + kt * 16 + 8 + q * 2]);
                mma_bf16(sacc[nt], aq[kt], b0, b1);
            }
        }

        // Online softmax (rows g and g+8; row data spread over quad lanes)
        float mt0 = -1e30f, mt1 = -1e30f;
        #pragma unroll
        for (int nt = 0; nt < 8; nt++) {
            mt0 = fmaxf(mt0, fmaxf(sacc[nt][0], sacc[nt][1]));
            mt1 = fmaxf(mt1, fmaxf(sacc[nt][2], sacc[nt][3]));
        }
        #pragma unroll
        for (int o = 1; o <= 2; o <<= 1) {
            mt0 = fmaxf(mt0, __shfl_xor_sync(0xffffffffu, mt0, o));
            mt1 = fmaxf(mt1, __shfl_xor_sync(0xffffffffu, mt1, o));
        }
        float mn0 = fmaxf(m0, mt0), mn1 = fmaxf(m1, mt1);
        float al0 = __expf(m0 - mn0), al1 = __expf(m1 - mn1);
        m0 = mn0; m1 = mn1;

        float ls0 = 0.f, ls1 = 0.f;
        #pragma unroll
        for (int nt = 0; nt < 8; nt++) {
            sacc[nt][0] = __expf(sacc[nt][0] - mn0);
            sacc[nt][1] = __expf(sacc[nt][1] - mn0);
            sacc[nt][2] = __expf(sacc[nt][2] - mn1);
            sacc[nt][3] = __expf(sacc[nt][3] - mn1);
            ls0 += sacc[nt][0] + sacc[nt][1];
            ls1 += sacc[nt][2] + sacc[nt][3];
        }
        #pragma unroll
        for (int o = 1; o <= 2; o <<= 1) {
            ls0 += __shfl_xor_sync(0xffffffffu, ls0, o);
            ls1 += __shfl_xor_sync(0xffffffffu, ls1, o);
        }
        l0 = l0 * al0 + ls0;
        l1 = l1 * al1 + ls1;
        #pragma unroll
        for (int nt = 0; nt < 8; nt++) {
            oacc[nt][0] *= al0; oacc[nt][1] *= al0;
            oacc[nt][2] *= al1; oacc[nt][3] *= al1;
        }

        // Pack P into bf16 A-fragments (C-layout == A-layout for m16n8k16)
        unsigned pa[4][4];
        #pragma unroll
        for (int kt = 0; kt < 4; kt++) {
            pa[kt][0] = pack_bf2(sacc[2 * kt][0],     sacc[2 * kt][1]);
            pa[kt][1] = pack_bf2(sacc[2 * kt][2],     sacc[2 * kt][3]);
            pa[kt][2] = pack_bf2(sacc[2 * kt + 1][0], sacc[2 * kt + 1][1]);
            pa[kt][3] = pack_bf2(sacc[2 * kt + 1][2], sacc[2 * kt + 1][3]);
        }

        // O += P @ V  (V accessed transposed: Vs[d][key])
        #pragma unroll
        for (int kt = 0; kt < 4; kt++) {
            #pragma unroll
            for (int nt = 0; nt < 8; nt++) {
                unsigned b0 = *reinterpret_cast<const unsigned*>(&Vb[(nt * 8 + g) * KS_LD + kt * 16 + q * 2]);
                unsigned b1 = *reinterpret_cast<const unsigned*>(&Vb[(nt * 8 + g) * KS_LD + kt * 16 + 8 + q * 2]);
                mma_bf16(oacc[nt], pa[kt], b0, b1);
            }
        }
        buf ^= 1;
    }

    // Normalize and write ctx[b*l, head*64 + d]
    float inv0 = 1.f / l0, inv1 = 1.f / l1;
    float* op = g_ctx + (size_t)(b * SEQ + q0 + w * 16) * D_MODEL + h * HDIM;
    #pragma unroll
    for (int nt = 0; nt < 8; nt++) {
        int c = nt * 8 + q * 2;
        *reinterpret_cast<float2*>(op + (size_t)g * D_MODEL + c) =
            make_float2(oacc[nt][0] * inv0, oacc[nt][1] * inv0);
        *reinterpret_cast<float2*>(op + (size_t)(g + 8) * D_MODEL + c) =
            make_float2(oacc[nt][2] * inv1, oacc[nt][3] * inv1);
    }
}

// ---------------------------------------------------------------------------
// Launch
// ---------------------------------------------------------------------------
extern "C" void kernel_launch(void* const* d_in, const int* in_sizes, int n_in,
                              void* d_out, int out_size) {
    const float* x     = (const float*)d_in[0];   // [2,2048,1024]
    const float* nw    = (const float*)d_in[1];   // [1024]
    const float* wqkv  = (const float*)d_in[2];   // [1024,3072]
    const float* wproj = (const float*)d_in[3];   // [1024,1024]
    float* out = (float*)d_out;

    float *inv, *qkv, *ctx;
    cudaGetSymbolAddress((void**)&inv, g_inv);
    cudaGetSymbolAddress((void**)&qkv, g_qkv);
    cudaGetSymbolAddress((void**)&ctx, g_ctx);

    cudaFuncSetAttribute(gemm_tf32, cudaFuncAttributeMaxDynamicSharedMemorySize,
                         GEMM_SMEM_BYTES);

    rms_inv_kernel<<<ROWS, 256>>>(x);

    // QKV GEMM with fused RMSNorm on A: A' = x * inv[row] * nw[col]
    dim3 gq(NQKV / GBN, ROWS / GBM);     // 24 x 32
    gemm_tf32<<<gq, 256, GEMM_SMEM_BYTES>>>(x, wqkv, nullptr, inv, nw, qkv,
                                            ROWS, NQKV, D_MODEL);

    dim3 ga(SEQ / 128, BATCH * NHEADS);  // 16 x 32
    attn_kernel<<<ga, 256>>>();

    // Proj GEMM + residual (no fusion scaling)
    dim3 gp(D_MODEL / GBN, ROWS / GBM);  // 8 x 32
    gemm_tf32<<<gp, 256, GEMM_SMEM_BYTES>>>(ctx, wproj, x, nullptr, nullptr, out,
                                            ROWS, D_MODEL, D_MODEL);
}

// round 9
// speedup vs baseline: 1.1946x; 1.1946x over previous
#include <cuda_runtime.h>
#include <cuda_bf16.h>

#define D_MODEL 1024
#define NHEADS  16
#define HDIM    64
#define SEQ     2048
#define BATCH   2
#define ROWS    (BATCH*SEQ)   // 4096
#define NQKV    (3*D_MODEL)   // 3072

// Scratch (device globals: no allocation allowed in kernel_launch)
__device__ float g_inv[ROWS];                               // per-row inv_rms
__device__ float g_qkv[ROWS * NQKV];                        // fused qkv fp32
__device__ float g_ctx[ROWS * D_MODEL];                     // attention output
__device__ __nv_bfloat16 g_kbf[BATCH*NHEADS*SEQ*HDIM];      // K bf16 [bh][s][d]
__device__ __nv_bfloat16 g_vtbf[BATCH*NHEADS*HDIM*SEQ];     // V bf16 transposed [bh][d][s]

// ---------------------------------------------------------------------------
// Helpers
// ---------------------------------------------------------------------------
__device__ __forceinline__ unsigned f2tf32(float f) {
    unsigned u;
    asm("cvt.rna.tf32.f32 %0, %1;" : "=r"(u) : "f"(f));
    return u;
}

__device__ __forceinline__ unsigned pack_bf2(float lo, float hi) {
    __nv_bfloat162 t = __floats2bfloat162_rn(lo, hi);
    return *reinterpret_cast<unsigned*>(&t);
}

__device__ __forceinline__ void mma_bf16(float* c, const unsigned* a, unsigned b0, unsigned b1) {
    asm volatile(
        "mma.sync.aligned.m16n8k16.row.col.f32.bf16.bf16.f32 "
        "{%0,%1,%2,%3}, {%4,%5,%6,%7}, {%8,%9}, {%0,%1,%2,%3};"
        : "+f"(c[0]), "+f"(c[1]), "+f"(c[2]), "+f"(c[3])
        : "r"(a[0]), "r"(a[1]), "r"(a[2]), "r"(a[3]), "r"(b0), "r"(b1));
}

__device__ __forceinline__ void mma_tf32(float* c, const unsigned* a, unsigned b0, unsigned b1) {
    asm volatile(
        "mma.sync.aligned.m16n8k8.row.col.f32.tf32.tf32.f32 "
        "{%0,%1,%2,%3}, {%4,%5,%6,%7}, {%8,%9}, {%0,%1,%2,%3};"
        : "+f"(c[0]), "+f"(c[1]), "+f"(c[2]), "+f"(c[3])
        : "r"(a[0]), "r"(a[1]), "r"(a[2]), "r"(a[3]), "r"(b0), "r"(b1));
}

__device__ __forceinline__ void cp16(unsigned dst, const void* src) {
    asm volatile("cp.async.cg.shared.global [%0], [%1], 16;" :: "r"(dst), "l"(src));
}

// ---------------------------------------------------------------------------
// RMS inverse: one block per row of 1024 floats; writes only inv_rms scalar.
// ---------------------------------------------------------------------------
__global__ __launch_bounds__(256) void rms_inv_kernel(const float* __restrict__ x) {
    int row = blockIdx.x;
    const float4* xr = reinterpret_cast<const float4*>(x + (size_t)row * D_MODEL);
    float4 v = xr[threadIdx.x];
    float ss = v.x * v.x + v.y * v.y + v.z * v.z + v.w * v.w;
    __shared__ float red[8];
    #pragma unroll
    for (int o = 16; o; o >>= 1) ss += __shfl_xor_sync(0xffffffffu, ss, o);
    if ((threadIdx.x & 31) == 0) red[threadIdx.x >> 5] = ss;
    __syncthreads();
    if (threadIdx.x == 0) {
        float s = 0.f;
        #pragma unroll
        for (int i = 0; i < 8; i++) s += red[i];
        g_inv[row] = rsqrtf(s * (1.0f / D_MODEL) + 1e-6f);
    }
}

// ---------------------------------------------------------------------------
// KV pack: per (b,h, 128-seq tile), write K as bf16 [s][d] and V as bf16
// transposed [d][s] (smem-tiled transpose for coalesced writes).
// ---------------------------------------------------------------------------
__global__ __launch_bounds__(256) void kv_pack_kernel() {
    __shared__ float Vsm[128 * 65];
    int bh = blockIdx.y, s0 = blockIdx.x * 128;
    int t = threadIdx.x;
    int b = bh >> 4, h = bh & 15;
    const float* base = g_qkv + (size_t)(b * SEQ) * NQKV + h * HDIM;
    const float* kpp = base + D_MODEL;
    const float* vpp = base + 2 * D_MODEL;

    __nv_bfloat16* kout = g_kbf + ((size_t)bh * SEQ + s0) * HDIM;
    for (int i = t; i < 128 * 16; i += 256) {
        int s = i >> 4, f = i & 15;
        float4 v = *reinterpret_cast<const float4*>(kpp + (size_t)(s0 + s) * NQKV + f * 4);
        __nv_bfloat162* d = reinterpret_cast<__nv_bfloat162*>(kout + (size_t)s * HDIM + f * 4);
        d[0] = __floats2bfloat162_rn(v.x, v.y);
        d[1] = __floats2bfloat162_rn(v.z, v.w);
    }

    for (int i = t; i < 128 * 16; i += 256) {
        int s = i >> 4, f = i & 15;
        float4 v = *reinterpret_cast<const float4*>(vpp + (size_t)(s0 + s) * NQKV + f * 4);
        float* d = &Vsm[s * 65 + f * 4];
        d[0] = v.x; d[1] = v.y; d[2] = v.z; d[3] = v.w;
    }
    __syncthreads();

    __nv_bfloat16* vout = g_vtbf + (size_t)bh * HDIM * SEQ + s0;
    for (int i = t; i < 64 * 64; i += 256) {
        int d = i >> 6, sp = (i & 63) * 2;
        unsigned pk = pack_bf2(Vsm[sp * 65 + d], Vsm[(sp + 1) * 65 + d]);
        *reinterpret_cast<unsigned*>(vout + (size_t)d * SEQ + sp) = pk;
    }
}

// ---------------------------------------------------------------------------
// Generic TF32 GEMM: C[M,N] = A'[M,K] @ B[K,N] (+ Res), all row-major fp32,
// where A'[r][c] = A[r][c] * rowscale[r] * colscale[c] if rowscale != nullptr.
// BM=128, BN=128, BK=32, 256 threads. Register-prefetch pipeline + ping-pong
// smem double-buffer (one barrier per K-tile). Dynamic smem 70 KB.
// ---------------------------------------------------------------------------
#define GBM 128
#define GBN 128
#define GBK 32
#define AS_LD 36
#define BS_LD 136
#define AS_BUF (GBM * AS_LD)
#define BS_BUF (GBK * BS_LD)
#define GEMM_SMEM_BYTES ((2 * AS_BUF + 2 * BS_BUF) * 4)

__global__ __launch_bounds__(256) void gemm_tf32(const float* __restrict__ A,
                                                 const float* __restrict__ B,
                                                 const float* __restrict__ Res,
                                                 const float* __restrict__ rowscale,
                                                 const float* __restrict__ colscale,
                                                 float* __restrict__ C,
                                                 int M, int N, int K) {
    extern __shared__ unsigned smem_u[];
    unsigned* AsAll = smem_u;
    unsigned* BsAll = smem_u + 2 * AS_BUF;

    int tid  = threadIdx.x;
    int lane = tid & 31, w = tid >> 5;
    int g = lane >> 2, q = lane & 3;
    int wm = w & 3, wn = w >> 2;
    int bm = blockIdx.y * GBM, bn = blockIdx.x * GBN;

    float acc[2][8][4] = {};

    int ar = tid >> 1, ac = (tid & 1) * 16;
    int br = tid >> 3, bj = tid & 7;

    float rs = rowscale ? rowscale[bm + ar] : 1.0f;

    float4 pa[4], pb[4];
    {
        const float4* ag = reinterpret_cast<const float4*>(A + (size_t)(bm + ar) * K + ac);
        #pragma unroll
        for (int i = 0; i < 4; i++) pa[i] = ag[i];
        const float4* bg = reinterpret_cast<const float4*>(B + (size_t)br * N + bn);
        #pragma unroll
        for (int i = 0; i < 4; i++) pb[i] = bg[i * 8 + bj];
    }

    int buf = 0;
    for (int kt = 0; kt < K; kt += GBK) {
        unsigned* As = AsAll + buf * AS_BUF;
        unsigned* Bs = BsAll + buf * BS_BUF;

        #pragma unroll
        for (int i = 0; i < 4; i++) {
            float4 s = pa[i];
            if (rowscale) {
                const float4 cw = __ldg(reinterpret_cast<const float4*>(colscale + kt + ac + i * 4));
                s.x *= rs * cw.x; s.y *= rs * cw.y;
                s.z *= rs * cw.z; s.w *= rs * cw.w;
            }
            unsigned* d = &As[ar * AS_LD + ac + i * 4];
            d[0] = f2tf32(s.x); d[1] = f2tf32(s.y);
            d[2] = f2tf32(s.z); d[3] = f2tf32(s.w);
        }
        #pragma unroll
        for (int i = 0; i < 4; i++) {
            unsigned* d = &Bs[br * BS_LD + (i * 8 + bj) * 4];
            d[0] = f2tf32(pb[i].x); d[1] = f2tf32(pb[i].y);
            d[2] = f2tf32(pb[i].z); d[3] = f2tf32(pb[i].w);
        }
        __syncthreads();

        int kn = kt + GBK;
        if (kn < K) {
            const float4* ag = reinterpret_cast<const float4*>(A + (size_t)(bm + ar) * K + kn + ac);
            #pragma unroll
            for (int i = 0; i < 4; i++) pa[i] = ag[i];
            const float4* bg = reinterpret_cast<const float4*>(B + (size_t)(kn + br) * N + bn);
            #pragma unroll
            for (int i = 0; i < 4; i++) pb[i] = bg[i * 8 + bj];
        }

        #pragma unroll
        for (int ks = 0; ks < 4; ks++) {
            unsigned a[2][4], b[8][2];
            #pragma unroll
            for (int mt = 0; mt < 2; mt++) {
                int r = wm * 32 + mt * 16;
                a[mt][0] = As[(r + g)     * AS_LD + ks * 8 + q];
                a[mt][1] = As[(r + g + 8) * AS_LD + ks * 8 + q];
                a[mt][2] = As[(r + g)     * AS_LD + ks * 8 + q + 4];
                a[mt][3] = As[(r + g + 8) * AS_LD + ks * 8 + q + 4];
            }
            #pragma unroll
            for (int nt = 0; nt < 8; nt++) {
                int c = wn * 64 + nt * 8 + g;
                b[nt][0] = Bs[(ks * 8 + q)     * BS_LD + c];
                b[nt][1] = Bs[(ks * 8 + q + 4) * BS_LD + c];
            }
            #pragma unroll
            for (int mt = 0; mt < 2; mt++)
                #pragma unroll
                for (int nt = 0; nt < 8; nt++)
                    mma_tf32(acc[mt][nt], a[mt], b[nt][0], b[nt][1]);
        }
        buf ^= 1;
    }

    #pragma unroll
    for (int mt = 0; mt < 2; mt++) {
        int r0 = bm + wm * 32 + mt * 16 + g;
        #pragma unroll
        for (int nt = 0; nt < 8; nt++) {
            int c = bn + wn * 64 + nt * 8 + q * 2;
            float2 v0 = make_float2(acc[mt][nt][0], acc[mt][nt][1]);
            float2 v1 = make_float2(acc[mt][nt][2], acc[mt][nt][3]);
            if (Res) {
                float2 r0v = *reinterpret_cast<const float2*>(Res + (size_t)r0 * N + c);
                float2 r1v = *reinterpret_cast<const float2*>(Res + (size_t)(r0 + 8) * N + c);
                v0.x += r0v.x; v0.y += r0v.y;
                v1.x += r1v.x; v1.y += r1v.y;
            }
            *reinterpret_cast<float2*>(C + (size_t)r0 * N + c) = v0;
            *reinterpret_cast<float2*>(C + (size_t)(r0 + 8) * N + c) = v1;
        }
    }
}

// ---------------------------------------------------------------------------
// Flash attention: per (b,head), BM=128 q-rows, BN=64 keys per step.
// K/V pre-packed bf16 (V transposed) -> staging is pure cp.async, double
// buffered. 256 threads, target 2 CTAs/SM. 36 KB static smem.
// ---------------------------------------------------------------------------
#define KS_LD 72   // bf16 elements per padded row (conflict-free 32-bit LDS)
#define KV_BUF (64 * KS_LD)

__global__ __launch_bounds__(256, 2) void attn_kernel() {
    __shared__ __nv_bfloat16 Ks[2 * KV_BUF];   // Ks[key][d], 2 buffers
    __shared__ __nv_bfloat16 Vs[2 * KV_BUF];   // Vs[d][key], 2 buffers

    int tid  = threadIdx.x;
    int lane = tid & 31, w = tid >> 5;
    int g = lane >> 2, q = lane & 3;
    int bh = blockIdx.y;
    int b = bh >> 4, h = bh & 15;
    int q0 = blockIdx.x * 128;

    const float* qp = g_qkv + (size_t)(b * SEQ) * NQKV + h * HDIM;
    const __nv_bfloat16* kre = g_kbf  + (size_t)bh * SEQ * HDIM;
    const __nv_bfloat16* vre = g_vtbf + (size_t)bh * HDIM * SEQ;
    unsigned ksb = (unsigned)__cvta_generic_to_shared(Ks);
    unsigned vsb = (unsigned)__cvta_generic_to_shared(Vs);

    // Q fragments: 4 k16-tiles x 4 regs, pre-scaled by 1/8 (exact in bf16)
    unsigned aq[4][4];
    {
        const float s = 0.125f;
        int r0 = q0 + w * 16 + g;
        #pragma unroll
        for (int kt = 0; kt < 4; kt++) {
            int c = kt * 16 + q * 2;
            float2 v00 = *reinterpret_cast<const float2*>(qp + (size_t)r0 * NQKV + c);
            float2 v01 = *reinterpret_cast<const float2*>(qp + (size_t)r0 * NQKV + c + 8);
            float2 v10 = *reinterpret_cast<const float2*>(qp + (size_t)(r0 + 8) * NQKV + c);
            float2 v11 = *reinterpret_cast<const float2*>(qp + (size_t)(r0 + 8) * NQKV + c + 8);
            aq[kt][0] = pack_bf2(v00.x * s, v00.y * s);
            aq[kt][1] = pack_bf2(v10.x * s, v10.y * s);
            aq[kt][2] = pack_bf2(v01.x * s, v01.y * s);
            aq[kt][3] = pack_bf2(v11.x * s, v11.y * s);
        }
    }

    float oacc[8][4] = {};
    float m0 = -1e30f, m1 = -1e30f, l0 = 0.f, l1 = 0.f;

    // cp.async staging: 512 16B chunks per K tile (+512 for V), 2 per thread.
    // chunk c: row r = c>>3 (key for K, d for V), ch = c&7.
    auto issue = [&](int n0, int bf) {
        #pragma unroll
        for (int i = 0; i < 2; i++) {
            int c = tid + i * 256;
            int r = c >> 3, ch = c & 7;
            cp16(ksb + (unsigned)((bf * KV_BUF + r * KS_LD) * 2 + ch * 16),
                 kre + (size_t)(n0 + r) * HDIM + ch * 8);
            cp16(vsb + (unsigned)((bf * KV_BUF + r * KS_LD) * 2 + ch * 16),
                 vre + (size_t)r * SEQ + n0 + ch * 8);
        }
        asm volatile("cp.async.commit_group;" ::: "memory");
    };

    issue(0, 0);
    int buf = 0;
    for (int n0 = 0; n0 < SEQ; n0 += 64) {
        asm volatile("cp.async.wait_group 0;" ::: "memory");
        __syncthreads();   // all copies of current tile visible; prior readers done
        if (n0 + 64 < SEQ) issue(n0 + 64, buf ^ 1);

        const __nv_bfloat16* Kb = Ks + buf * KV_BUF;
        const __nv_bfloat16* Vb = Vs + buf * KV_BUF;

        // S = (Q*scale) @ K^T
        float sacc[8][4] = {};
        #pragma unroll
        for (int kt = 0; kt < 4; kt++) {
            #pragma unroll
            for (int nt = 0; nt < 8; nt++) {
                unsigned b0 = *reinterpret_cast<const unsigned*>(&Kb[(nt * 8 + g) * KS_LD + kt * 16 + q * 2]);
                unsigned b1 = *reinterpret_cast<const unsigned*>(&Kb[(nt * 8 + g) * KS_LD + kt * 16 + 8 + q * 2]);
                mma_bf16(sacc[nt], aq[kt], b0, b1);
            }
        }

        // Online softmax (rows g and g+8)
        float mt0 = -1e30f, mt1 = -1e30f;
        #pragma unroll
        for (int nt = 0; nt < 8; nt++) {
            mt0 = fmaxf(mt0, fmaxf(sacc[nt][0], sacc[nt][1]));
            mt1 = fmaxf(mt1, fmaxf(sacc[nt][2], sacc[nt][3]));
        }
        #pragma unroll
        for (int o = 1; o <= 2; o <<= 1) {
            mt0 = fmaxf(mt0, __shfl_xor_sync(0xffffffffu, mt0, o));
            mt1 = fmaxf(mt1, __shfl_xor_sync(0xffffffffu, mt1, o));
        }
        float mn0 = fmaxf(m0, mt0), mn1 = fmaxf(m1, mt1);
        float al0 = __expf(m0 - mn0), al1 = __expf(m1 - mn1);
        m0 = mn0; m1 = mn1;

        float ls0 = 0.f, ls1 = 0.f;
        #pragma unroll
        for (int nt = 0; nt < 8; nt++) {
            sacc[nt][0] = __expf(sacc[nt][0] - mn0);
            sacc[nt][1] = __expf(sacc[nt][1] - mn0);
            sacc[nt][2] = __expf(sacc[nt][2] - mn1);
            sacc[nt][3] = __expf(sacc[nt][3] - mn1);
            ls0 += sacc[nt][0] + sacc[nt][1];
            ls1 += sacc[nt][2] + sacc[nt][3];
        }
        #pragma unroll
        for (int o = 1; o <= 2; o <<= 1) {
            ls0 += __shfl_xor_sync(0xffffffffu, ls0, o);
            ls1 += __shfl_xor_sync(0xffffffffu, ls1, o);
        }
        l0 = l0 * al0 + ls0;
        l1 = l1 * al1 + ls1;
        #pragma unroll
        for (int nt = 0; nt < 8; nt++) {
            oacc[nt][0] *= al0; oacc[nt][1] *= al0;
            oacc[nt][2] *= al1; oacc[nt][3] *= al1;
        }

        // Pack P into bf16 A-fragments (C-layout == A-layout)
        unsigned pa[4][4];
        #pragma unroll
        for (int kt = 0; kt < 4; kt++) {
            pa[kt][0] = pack_bf2(sacc[2 * kt][0],     sacc[2 * kt][1]);
            pa[kt][1] = pack_bf2(sacc[2 * kt][2],     sacc[2 * kt][3]);
            pa[kt][2] = pack_bf2(sacc[2 * kt + 1][0], sacc[2 * kt + 1][1]);
            pa[kt][3] = pack_bf2(sacc[2 * kt + 1][2], sacc[2 * kt + 1][3]);
        }

        // O += P @ V
        #pragma unroll
        for (int kt = 0; kt < 4; kt++) {
            #pragma unroll
            for (int nt = 0; nt < 8; nt++) {
                unsigned b0 = *reinterpret_cast<const unsigned*>(&Vb[(nt * 8 + g) * KS_LD + kt * 16 + q * 2]);
                unsigned b1 = *reinterpret_cast<const unsigned*>(&Vb[(nt * 8 + g) * KS_LD + kt * 16 + 8 + q * 2]);
                mma_bf16(oacc[nt], pa[kt], b0, b1);
            }
        }
        buf ^= 1;
    }

    // Normalize and write ctx
    float inv0 = 1.f / l0, inv1 = 1.f / l1;
    float* op = g_ctx + (size_t)(b * SEQ + q0 + w * 16) * D_MODEL + h * HDIM;
    #pragma unroll
    for (int nt = 0; nt < 8; nt++) {
        int c = nt * 8 + q * 2;
        *reinterpret_cast<float2*>(op + (size_t)g * D_MODEL + c) =
            make_float2(oacc[nt][0] * inv0, oacc[nt][1] * inv0);
        *reinterpret_cast<float2*>(op + (size_t)(g + 8) * D_MODEL + c) =
            make_float2(oacc[nt][2] * inv1, oacc[nt][3] * inv1);
    }
}

// ---------------------------------------------------------------------------
// Launch
// ---------------------------------------------------------------------------
extern "C" void kernel_launch(void* const* d_in, const int* in_sizes, int n_in,
                              void* d_out, int out_size) {
    const float* x     = (const float*)d_in[0];
    const float* nw    = (const float*)d_in[1];
    const float* wqkv  = (const float*)d_in[2];
    const float* wproj = (const float*)d_in[3];
    float* out = (float*)d_out;

    float *inv, *qkv, *ctx;
    cudaGetSymbolAddress((void**)&inv, g_inv);
    cudaGetSymbolAddress((void**)&qkv, g_qkv);
    cudaGetSymbolAddress((void**)&ctx, g_ctx);

    cudaFuncSetAttribute(gemm_tf32, cudaFuncAttributeMaxDynamicSharedMemorySize,
                         GEMM_SMEM_BYTES);

    rms_inv_kernel<<<ROWS, 256>>>(x);

    dim3 gq(NQKV / GBN, ROWS / GBM);     // 24 x 32
    gemm_tf32<<<gq, 256, GEMM_SMEM_BYTES>>>(x, wqkv, nullptr, inv, nw, qkv,
                                            ROWS, NQKV, D_MODEL);

    dim3 gk(SEQ / 128, BATCH * NHEADS);  // 16 x 32
    kv_pack_kernel<<<gk, 256>>>();

    dim3 ga(SEQ / 128, BATCH * NHEADS);  // 16 x 32
    attn_kernel<<<ga, 256>>>();

    dim3 gp(D_MODEL / GBN, ROWS / GBM);  // 8 x 32
    gemm_tf32<<<gp, 256, GEMM_SMEM_BYTES>>>(ctx, wproj, x, nullptr, nullptr, out,
                                            ROWS, D_MODEL, D_MODEL);
}